// round 11
// baseline (speedup 1.0000x reference)
#include <cuda_runtime.h>
#include <cuda_bf16.h>
#include <cstdint>

#define PP        4096
#define HH        256
#define NSTEPS    100
#define DTC       0.1f
#define SQRT_DTC  0.31622776601683794f
#define M_CTA     16
#define NCTA      (PP / M_CTA)   // 256
#define NTHREADS  256
#define AS        264            // bf16 row stride (528B): conflict-free ldsm/STS

// smem per CTA: 4 act bufs (33792) + w0 (8192) + b0/b1/b2 (3072) + b3 (32)
//       + out5 (512) + st (128) + inp0 (512) + w3frag (8192) = 54432
#define SMEM_BYTES 54432

// Weight fragments in exact mma.m16n8k16 B-operand order: [k_tile][n8][lane] -> {b0,b1}
__device__ uint2 g_W1h[16 * 32 * 32];
__device__ uint2 g_W1l[16 * 32 * 32];
__device__ uint2 g_W2h[16 * 32 * 32];
__device__ uint2 g_W2l[16 * 32 * 32];
__device__ uint2 g_W3h[16 * 32];
__device__ uint2 g_W3l[16 * 32];

__device__ __forceinline__ float softplusf(float x) {
    return fmaxf(x, 0.0f) + log1pf(expf(-fabsf(x)));
}
__device__ __forceinline__ uint32_t bfpack(float a, float b) {
    __nv_bfloat162 v = __floats2bfloat162_rn(a, b);   // .x = a (low half)
    return *reinterpret_cast<uint32_t*>(&v);
}

// ---------------- prep: fp32 weights -> hi/lo bf16 fragment arrays ----------------
__global__ void prep_kernel(const float* __restrict__ W1,
                            const float* __restrict__ W2,
                            const float* __restrict__ W3) {
    const int idx = blockIdx.x * blockDim.x + threadIdx.x;
    const int TOT = 16 * 32 * 32;
    if (idx < 2 * TOT) {
        const int l = idx / TOT, r = idx % TOT;
        const int kt = r >> 10;
        const int n8 = (r >> 5) & 31;
        const int lane = r & 31;
        const int k0 = kt * 16 + (lane & 3) * 2;
        const int n = n8 * 8 + (lane >> 2);
        const float* W = l ? W2 : W1;
        float x[4];
        x[0] = W[(k0)     * HH + n];
        x[1] = W[(k0 + 1) * HH + n];
        x[2] = W[(k0 + 8) * HH + n];
        x[3] = W[(k0 + 9) * HH + n];
        float h[4], lo[4];
#pragma unroll
        for (int i = 0; i < 4; i++) {
            h[i]  = __bfloat162float(__float2bfloat16(x[i]));
            lo[i] = x[i] - h[i];
        }
        uint2 hv, lv;
        hv.x = bfpack(h[0], h[1]);  hv.y = bfpack(h[2], h[3]);
        lv.x = bfpack(lo[0], lo[1]); lv.y = bfpack(lo[2], lo[3]);
        if (l) { g_W2h[r] = hv; g_W2l[r] = lv; }
        else   { g_W1h[r] = hv; g_W1l[r] = lv; }
    } else if (idx < 2 * TOT + 512) {
        const int r = idx - 2 * TOT;
        const int kt = r >> 5, lane = r & 31;
        const int k0 = kt * 16 + (lane & 3) * 2;
        const int n = lane >> 2;
        float x[4] = {0.f, 0.f, 0.f, 0.f};
        if (n < 5) {
            x[0] = W3[(k0)     * 5 + n];
            x[1] = W3[(k0 + 1) * 5 + n];
            x[2] = W3[(k0 + 8) * 5 + n];
            x[3] = W3[(k0 + 9) * 5 + n];
        }
        float h[4], lo[4];
#pragma unroll
        for (int i = 0; i < 4; i++) {
            h[i]  = __bfloat162float(__float2bfloat16(x[i]));
            lo[i] = x[i] - h[i];
        }
        uint2 hv, lv;
        hv.x = bfpack(h[0], h[1]);  hv.y = bfpack(h[2], h[3]);
        lv.x = bfpack(lo[0], lo[1]); lv.y = bfpack(lo[2], lo[3]);
        g_W3h[r] = hv; g_W3l[r] = lv;
    }
}

// ---------------- tensor-core primitives ----------------
__device__ __forceinline__ void ldsm4(uint32_t* r, const __nv_bfloat16* p) {
    uint32_t addr = (uint32_t)__cvta_generic_to_shared(p);
    asm volatile("ldmatrix.sync.aligned.m8n8.x4.shared.b16 {%0,%1,%2,%3}, [%4];"
                 : "=r"(r[0]), "=r"(r[1]), "=r"(r[2]), "=r"(r[3]) : "r"(addr));
}
__device__ __forceinline__ void mma_bf16(float* d, const uint32_t* a,
                                         uint32_t b0, uint32_t b1) {
    asm volatile(
        "mma.sync.aligned.m16n8k16.row.col.f32.bf16.bf16.f32 "
        "{%0,%1,%2,%3}, {%4,%5,%6,%7}, {%8,%9}, {%0,%1,%2,%3};"
        : "+f"(d[0]), "+f"(d[1]), "+f"(d[2]), "+f"(d[3])
        : "r"(a[0]), "r"(a[1]), "r"(a[2]), "r"(a[3]), "r"(b0), "r"(b1));
}

// fragment bundle for one kt: A hi/lo (1 m-tile) + B hi/lo (4 n-tiles)
struct Frag {
    uint32_t ah[4], al[4];
    uint2 bh[4], bl[4];
};

__device__ __forceinline__ void load_frag(
    Frag& f, const __nv_bfloat16* Ah, const __nv_bfloat16* Al,
    const uint2* __restrict__ bhp, const uint2* __restrict__ blp,
    int arow, int co, int kt) {
    ldsm4(f.ah, Ah + arow * AS + co);
    ldsm4(f.al, Al + arow * AS + co);
    const uint2* bh = bhp + kt * 1024;
    const uint2* bl = blp + kt * 1024;
#pragma unroll
    for (int nt = 0; nt < 4; nt++) {
        f.bh[nt] = __ldg(bh + nt * 32);
        f.bl[nt] = __ldg(bl + nt * 32);
    }
}

__device__ __forceinline__ void mma_frag(float D[4][4], const Frag& f) {
#pragma unroll
    for (int nt = 0; nt < 4; nt++) {
        mma_bf16(D[nt], f.ah, f.bh[nt].x, f.bh[nt].y);
        mma_bf16(D[nt], f.ah, f.bl[nt].x, f.bl[nt].y);
        mma_bf16(D[nt], f.al, f.bh[nt].x, f.bh[nt].y);
    }
}

// One 256->256 layer + bias + relu, 3-term split-bf16, double-buffered pipeline.
// Warp owns output cols [32*warp, 32*warp+32), 16 rows (one m16 tile).
__device__ __forceinline__ void tc_layer(
    const __nv_bfloat16* Ah, const __nv_bfloat16* Al,
    __nv_bfloat16* Oh, __nv_bfloat16* Ol,
    const uint2* __restrict__ Bh, const uint2* __restrict__ Bl,
    const float* b_sh, int warp, int lane) {
    float D[4][4];
#pragma unroll
    for (int nt = 0; nt < 4; nt++)
#pragma unroll
        for (int i = 0; i < 4; i++) D[nt][i] = 0.0f;

    const int arow = (lane & 7) + ((lane >> 3) & 1) * 8;
    const int acol = (lane >> 4) * 8;
    const uint2* bhp = Bh + 4 * warp * 32 + lane;   // + kt*1024 per tile
    const uint2* blp = Bl + 4 * warp * 32 + lane;

    Frag f0, f1;
    load_frag(f0, Ah, Al, bhp, blp, arow, acol, 0);
#pragma unroll 2
    for (int i = 0; i < 8; i++) {
        const int kt = 2 * i;
        load_frag(f1, Ah, Al, bhp, blp, arow, (kt + 1) * 16 + acol, kt + 1);
        mma_frag(D, f0);
        if (i < 7)
            load_frag(f0, Ah, Al, bhp, blp, arow, (kt + 2) * 16 + acol, kt + 2);
        mma_frag(D, f1);
    }

    // epilogue: bias + relu + hi/lo split, conflict-free STS.32
    const int rbase = lane >> 2;
#pragma unroll
    for (int nt = 0; nt < 4; nt++) {
        const int col = (4 * warp + nt) * 8 + (lane & 3) * 2;
        const float bb0 = b_sh[col], bb1 = b_sh[col + 1];
#pragma unroll
        for (int h = 0; h < 2; h++) {
            const int row = rbase + h * 8;
            float x0 = fmaxf(D[nt][2 * h + 0] + bb0, 0.0f);
            float x1 = fmaxf(D[nt][2 * h + 1] + bb1, 0.0f);
            float h0 = __bfloat162float(__float2bfloat16(x0));
            float h1 = __bfloat162float(__float2bfloat16(x1));
            *reinterpret_cast<uint32_t*>(Oh + row * AS + col) = bfpack(h0, h1);
            *reinterpret_cast<uint32_t*>(Ol + row * AS + col) =
                bfpack(x0 - h0, x1 - h1);
        }
    }
}

// ---------------- main persistent kernel ----------------
__global__ void __launch_bounds__(NTHREADS, 2) lv_tc_kernel(
    const float* __restrict__ W0, const float* __restrict__ b0,
    const float* __restrict__ b1, const float* __restrict__ b2,
    const float* __restrict__ b3,
    const float* __restrict__ obs_init, const float* __restrict__ feature_init,
    const float* __restrict__ tn_store, const float* __restrict__ x1_store,
    const float* __restrict__ x2_store, const float* __restrict__ path_seed,
    float* __restrict__ out) {
    extern __shared__ __align__(16) unsigned char smem_raw[];
    __nv_bfloat16* Ah = reinterpret_cast<__nv_bfloat16*>(smem_raw);
    __nv_bfloat16* Al = Ah + M_CTA * AS;
    __nv_bfloat16* Bh = Al + M_CTA * AS;
    __nv_bfloat16* Bl = Bh + M_CTA * AS;
    float* w0_sh = reinterpret_cast<float*>(Bl + M_CTA * AS);
    float* b0_sh = w0_sh + 8 * HH;
    float* b1_sh = b0_sh + HH;
    float* b2_sh = b1_sh + HH;
    float* b3_sh = b2_sh + HH;       // 8
    float* out5  = b3_sh + 8;        // 16*8
    float* st_sh = out5 + M_CTA * 8; // 32
    float* inp0  = st_sh + 32;       // 16*8
    uint2* w3f   = reinterpret_cast<uint2*>(inp0 + M_CTA * 8);  // 1024 uint2

    const int tid = threadIdx.x;
    const int warp = tid >> 5, lane = tid & 31;
    const int row0 = blockIdx.x * M_CTA;

    // one-time staging
    for (int i = tid; i < 8 * HH; i += NTHREADS) w0_sh[i] = W0[i];
    if (tid < HH) { b0_sh[tid] = b0[tid]; b1_sh[tid] = b1[tid]; b2_sh[tid] = b2[tid]; }
    if (tid < 8) b3_sh[tid] = (tid < 5) ? b3[tid] : 0.0f;
    if (tid < M_CTA * 2) st_sh[tid] = obs_init[row0 * 2 + tid];
    if (tid < M_CTA * 8) {
        int r = tid >> 3, k = tid & 7;
        inp0[tid] = (k < 2) ? obs_init[(row0 + r) * 2 + k]
                            : feature_init[(row0 + r) * 6 + (k - 2)];
    }
    // layer-3 fragments -> smem once: hi at [0,512), lo at [512,1024)
    for (int i = tid; i < 1024; i += NTHREADS)
        w3f[i] = (i < 512) ? g_W3h[i] : g_W3l[i - 512];
    float t_reg = __ldg(feature_init);   // t0 = feature_init[0,0,0]
    __syncthreads();

#pragma unroll 1
    for (int s = 0; s < NSTEPS; s++) {
        // ---- layer 0 (scalar fp32): col n = tid, 16 rows -> Ah/Al
        {
            const int n = tid;
            if (s == 0) {
#pragma unroll 4
                for (int r = 0; r < M_CTA; r++) {
                    float a = b0_sh[n];
#pragma unroll
                    for (int k = 0; k < 8; k++)
                        a = fmaf(inp0[r * 8 + k], w0_sh[k * HH + n], a);
                    a = fmaxf(a, 0.0f);
                    float h = __bfloat162float(__float2bfloat16(a));
                    Ah[r * AS + n] = __float2bfloat16(a);
                    Al[r * AS + n] = __float2bfloat16(a - h);
                }
            } else {
                t_reg += DTC;   // exact sequential fp32 time accumulation
                const int i = s - 1;
                const float f_tn = __ldg(tn_store + i);
                const float f_x1 = __ldg(x1_store + i);
                const float f_x2 = __ldg(x2_store + i);
                float base = b0_sh[n];
                base = fmaf(t_reg, w0_sh[2 * HH + n], base);
                base = fmaf(f_tn,  w0_sh[3 * HH + n], base);
                base = fmaf(f_x1,  w0_sh[4 * HH + n], base);
                base = fmaf(f_x2,  w0_sh[5 * HH + n], base);
                base = fmaf(f_x1,  w0_sh[6 * HH + n], base);
                base = fmaf(f_x2,  w0_sh[7 * HH + n], base);
                const float wa = w0_sh[n], wb = w0_sh[HH + n];
#pragma unroll 4
                for (int r = 0; r < M_CTA; r++) {
                    float a = fmaf(st_sh[2 * r], wa, fmaf(st_sh[2 * r + 1], wb, base));
                    a = fmaxf(a, 0.0f);
                    float h = __bfloat162float(__float2bfloat16(a));
                    Ah[r * AS + n] = __float2bfloat16(a);
                    Al[r * AS + n] = __float2bfloat16(a - h);
                }
            }
        }
        __syncthreads();

        tc_layer(Ah, Al, Bh, Bl, g_W1h, g_W1l, b1_sh, warp, lane);
        __syncthreads();
        tc_layer(Bh, Bl, Ah, Al, g_W2h, g_W2l, b2_sh, warp, lane);
        __syncthreads();

        // ---- layer 3: (16 x 256) @ (256 x 5pad8), warp 0 (one m16 tile)
        if (warp == 0) {
            float D[4] = {0.f, 0.f, 0.f, 0.f};
            const int arow = (lane & 7) + ((lane >> 3) & 1) * 8;
            const int acol = (lane >> 4) * 8;
#pragma unroll
            for (int kt = 0; kt < 16; kt++) {
                uint32_t ah[4], al[4];
                ldsm4(ah, Ah + arow * AS + kt * 16 + acol);
                ldsm4(al, Al + arow * AS + kt * 16 + acol);
                uint2 bh = w3f[kt * 32 + lane];
                uint2 bl = w3f[512 + kt * 32 + lane];
                mma_bf16(D, ah, bh.x, bh.y);
                mma_bf16(D, ah, bl.x, bl.y);
                mma_bf16(D, al, bh.x, bh.y);
            }
            const int row = lane >> 2;
            const int col = (lane & 3) * 2;
            out5[row * 8 + col]           = D[0];
            out5[row * 8 + col + 1]       = D[1];
            out5[(row + 8) * 8 + col]     = D[2];
            out5[(row + 8) * 8 + col + 1] = D[3];
        }
        __syncthreads();

        // ---- SDE sample + global writes (fp32, exact reference semantics)
        if (tid < M_CTA) {
            const int r = tid, p = row0 + r;
            float mu0 = out5[r * 8 + 0] + b3_sh[0];
            float mu1 = out5[r * 8 + 1] + b3_sh[1];
            float s11 = softplusf(out5[r * 8 + 2] + b3_sh[2]);
            float s21 = out5[r * 8 + 3] + b3_sh[3];
            float s22 = softplusf(out5[r * 8 + 4] + b3_sh[4]);
            float st0 = st_sh[2 * r], st1 = st_sh[2 * r + 1];
            float2 e = __ldg(reinterpret_cast<const float2*>(path_seed) + s * PP + p);
            float n0v = softplusf(st0 + DTC * mu0 + SQRT_DTC * (s11 * e.x));
            float n1v = softplusf(st1 + DTC * mu1 + SQRT_DTC * (s21 * e.x + s22 * e.y));
            st_sh[2 * r]     = n0v;
            st_sh[2 * r + 1] = n1v;

            out[p * 202 + (s + 1)]       = n0v;
            out[p * 202 + 101 + (s + 1)] = n1v;
            if (s == 0) {
                out[p * 202 + 0]   = st0;
                out[p * 202 + 101] = st1;
            }
            int mb = PP * 202 + (p * 100 + s) * 2;
            out[mb + 0] = mu0;
            out[mb + 1] = mu1;
            int sb = PP * 202 + PP * 200 + (p * 100 + s) * 4;
            out[sb + 0] = s11;
            out[sb + 1] = 0.0f;
            out[sb + 2] = s21;
            out[sb + 3] = s22;
        }
        __syncthreads();
    }
}

extern "C" void kernel_launch(void* const* d_in, const int* in_sizes, int n_in,
                              void* d_out, int out_size) {
    const float* W0 = (const float*)d_in[0];
    const float* b0 = (const float*)d_in[1];
    const float* W1 = (const float*)d_in[2];
    const float* b1 = (const float*)d_in[3];
    const float* W2 = (const float*)d_in[4];
    const float* b2 = (const float*)d_in[5];
    const float* W3 = (const float*)d_in[6];
    const float* b3 = (const float*)d_in[7];
    const float* obs_init = (const float*)d_in[8];
    const float* feature_init = (const float*)d_in[9];
    const float* tn_store = (const float*)d_in[10];
    const float* x1_store = (const float*)d_in[11];
    const float* x2_store = (const float*)d_in[12];
    const float* path_seed = (const float*)d_in[13];
    float* out = (float*)d_out;

    // 1) split weights into hi/lo bf16 fragment arrays
    prep_kernel<<<130, 256>>>(W1, W2, W3);

    // 2) persistent 100-step trajectory kernel
    cudaFuncSetAttribute(lv_tc_kernel, cudaFuncAttributeMaxDynamicSharedMemorySize,
                         SMEM_BYTES);
    lv_tc_kernel<<<NCTA, NTHREADS, SMEM_BYTES>>>(
        W0, b0, b1, b2, b3, obs_init, feature_init,
        tn_store, x1_store, x2_store, path_seed, out);
}

// round 12
// speedup vs baseline: 1.6383x; 1.6383x over previous
#include <cuda_runtime.h>
#include <cuda_bf16.h>
#include <cstdint>

#define PP        4096
#define HH        256
#define NSTEPS    100
#define DTC       0.1f
#define SQRT_DTC  0.31622776601683794f
#define M_CTA     32
#define NCTA      (PP / M_CTA)   // 128
#define NTHREADS  512            // 16 warps, 2 n-tiles each
#define AS        264            // bf16 row stride (528B): conflict-free ldsm/STS

// smem: 4 act bufs (67584) + w0 (8192) + b0/b1/b2 (3072) + b3 (32)
//       + out5 (1024) + st (256) + inp0 (1024) + w3frag (8192) = 89376
#define SMEM_BYTES 89376

// Weight fragments in exact mma.m16n8k16 B-operand order: [k_tile][n8][lane] -> {b0,b1}
__device__ uint2 g_W1h[16 * 32 * 32];
__device__ uint2 g_W1l[16 * 32 * 32];
__device__ uint2 g_W2h[16 * 32 * 32];
__device__ uint2 g_W2l[16 * 32 * 32];
__device__ uint2 g_W3h[16 * 32];
__device__ uint2 g_W3l[16 * 32];

__device__ __forceinline__ float softplusf(float x) {
    return fmaxf(x, 0.0f) + log1pf(expf(-fabsf(x)));
}
__device__ __forceinline__ uint32_t bfpack(float a, float b) {
    __nv_bfloat162 v = __floats2bfloat162_rn(a, b);   // .x = a (low half)
    return *reinterpret_cast<uint32_t*>(&v);
}

// ---------------- prep: fp32 weights -> hi/lo bf16 fragment arrays ----------------
__global__ void prep_kernel(const float* __restrict__ W1,
                            const float* __restrict__ W2,
                            const float* __restrict__ W3) {
    const int idx = blockIdx.x * blockDim.x + threadIdx.x;
    const int TOT = 16 * 32 * 32;
    if (idx < 2 * TOT) {
        const int l = idx / TOT, r = idx % TOT;
        const int kt = r >> 10;
        const int n8 = (r >> 5) & 31;
        const int lane = r & 31;
        const int k0 = kt * 16 + (lane & 3) * 2;
        const int n = n8 * 8 + (lane >> 2);
        const float* W = l ? W2 : W1;
        float x[4];
        x[0] = W[(k0)     * HH + n];
        x[1] = W[(k0 + 1) * HH + n];
        x[2] = W[(k0 + 8) * HH + n];
        x[3] = W[(k0 + 9) * HH + n];
        float h[4], lo[4];
#pragma unroll
        for (int i = 0; i < 4; i++) {
            h[i]  = __bfloat162float(__float2bfloat16(x[i]));
            lo[i] = x[i] - h[i];
        }
        uint2 hv, lv;
        hv.x = bfpack(h[0], h[1]);  hv.y = bfpack(h[2], h[3]);
        lv.x = bfpack(lo[0], lo[1]); lv.y = bfpack(lo[2], lo[3]);
        if (l) { g_W2h[r] = hv; g_W2l[r] = lv; }
        else   { g_W1h[r] = hv; g_W1l[r] = lv; }
    } else if (idx < 2 * TOT + 512) {
        const int r = idx - 2 * TOT;
        const int kt = r >> 5, lane = r & 31;
        const int k0 = kt * 16 + (lane & 3) * 2;
        const int n = lane >> 2;
        float x[4] = {0.f, 0.f, 0.f, 0.f};
        if (n < 5) {
            x[0] = W3[(k0)     * 5 + n];
            x[1] = W3[(k0 + 1) * 5 + n];
            x[2] = W3[(k0 + 8) * 5 + n];
            x[3] = W3[(k0 + 9) * 5 + n];
        }
        float h[4], lo[4];
#pragma unroll
        for (int i = 0; i < 4; i++) {
            h[i]  = __bfloat162float(__float2bfloat16(x[i]));
            lo[i] = x[i] - h[i];
        }
        uint2 hv, lv;
        hv.x = bfpack(h[0], h[1]);  hv.y = bfpack(h[2], h[3]);
        lv.x = bfpack(lo[0], lo[1]); lv.y = bfpack(lo[2], lo[3]);
        g_W3h[r] = hv; g_W3l[r] = lv;
    }
}

// ---------------- tensor-core primitives ----------------
__device__ __forceinline__ void ldsm4(uint32_t* r, const __nv_bfloat16* p) {
    uint32_t addr = (uint32_t)__cvta_generic_to_shared(p);
    asm volatile("ldmatrix.sync.aligned.m8n8.x4.shared.b16 {%0,%1,%2,%3}, [%4];"
                 : "=r"(r[0]), "=r"(r[1]), "=r"(r[2]), "=r"(r[3]) : "r"(addr));
}
__device__ __forceinline__ void mma_bf16(float* d, const uint32_t* a,
                                         uint32_t b0, uint32_t b1) {
    asm volatile(
        "mma.sync.aligned.m16n8k16.row.col.f32.bf16.bf16.f32 "
        "{%0,%1,%2,%3}, {%4,%5,%6,%7}, {%8,%9}, {%0,%1,%2,%3};"
        : "+f"(d[0]), "+f"(d[1]), "+f"(d[2]), "+f"(d[3])
        : "r"(a[0]), "r"(a[1]), "r"(a[2]), "r"(a[3]), "r"(b0), "r"(b1));
}

// fragment bundle for one kt: A hi/lo (2 m-tiles) + B hi/lo (2 n-tiles)
struct Frag {
    uint32_t ah0[4], ah1[4], al0[4], al1[4];
    uint2 bh[2], bl[2];
};

__device__ __forceinline__ void load_frag(
    Frag& f, const __nv_bfloat16* Ah, const __nv_bfloat16* Al,
    const uint2* __restrict__ bhp, const uint2* __restrict__ blp,
    int arow, int co, int kt) {
    ldsm4(f.ah0, Ah + arow * AS + co);
    ldsm4(f.ah1, Ah + (arow + 16) * AS + co);
    ldsm4(f.al0, Al + arow * AS + co);
    ldsm4(f.al1, Al + (arow + 16) * AS + co);
    const uint2* bh = bhp + kt * 1024;
    const uint2* bl = blp + kt * 1024;
#pragma unroll
    for (int nt = 0; nt < 2; nt++) {
        f.bh[nt] = __ldg(bh + nt * 32);
        f.bl[nt] = __ldg(bl + nt * 32);
    }
}

__device__ __forceinline__ void mma_frag(float D[2][2][4], const Frag& f) {
#pragma unroll
    for (int nt = 0; nt < 2; nt++) {
        mma_bf16(D[0][nt], f.ah0, f.bh[nt].x, f.bh[nt].y);
        mma_bf16(D[1][nt], f.ah1, f.bh[nt].x, f.bh[nt].y);
        mma_bf16(D[0][nt], f.ah0, f.bl[nt].x, f.bl[nt].y);
        mma_bf16(D[1][nt], f.ah1, f.bl[nt].x, f.bl[nt].y);
        mma_bf16(D[0][nt], f.al0, f.bh[nt].x, f.bh[nt].y);
        mma_bf16(D[1][nt], f.al1, f.bh[nt].x, f.bh[nt].y);
    }
}

// One 256->256 layer + bias + relu, 3-term split-bf16, double-buffered pipeline.
// 16 warps; warp w owns output cols [16w, 16w+16) (n-tiles 2w, 2w+1), 32 rows.
__device__ __forceinline__ void tc_layer(
    const __nv_bfloat16* Ah, const __nv_bfloat16* Al,
    __nv_bfloat16* Oh, __nv_bfloat16* Ol,
    const uint2* __restrict__ Bh, const uint2* __restrict__ Bl,
    const float* b_sh, int warp, int lane) {
    float D[2][2][4];
#pragma unroll
    for (int mt = 0; mt < 2; mt++)
#pragma unroll
        for (int nt = 0; nt < 2; nt++)
#pragma unroll
            for (int i = 0; i < 4; i++) D[mt][nt][i] = 0.0f;

    const int arow = (lane & 7) + ((lane >> 3) & 1) * 8;
    const int acol = (lane >> 4) * 8;
    const uint2* bhp = Bh + 2 * warp * 32 + lane;   // + kt*1024 per tile
    const uint2* blp = Bl + 2 * warp * 32 + lane;

    Frag f0, f1;
    load_frag(f0, Ah, Al, bhp, blp, arow, acol, 0);
#pragma unroll 2
    for (int i = 0; i < 8; i++) {
        const int kt = 2 * i;
        load_frag(f1, Ah, Al, bhp, blp, arow, (kt + 1) * 16 + acol, kt + 1);
        mma_frag(D, f0);
        if (i < 7)
            load_frag(f0, Ah, Al, bhp, blp, arow, (kt + 2) * 16 + acol, kt + 2);
        mma_frag(D, f1);
    }

    // epilogue: bias + relu + hi/lo split, conflict-free STS.32
    const int rbase = lane >> 2;
#pragma unroll
    for (int mt = 0; mt < 2; mt++) {
#pragma unroll
        for (int nt = 0; nt < 2; nt++) {
            const int col = (2 * warp + nt) * 8 + (lane & 3) * 2;
            const float bb0 = b_sh[col], bb1 = b_sh[col + 1];
#pragma unroll
            for (int h = 0; h < 2; h++) {
                const int row = mt * 16 + rbase + h * 8;
                float x0 = fmaxf(D[mt][nt][2 * h + 0] + bb0, 0.0f);
                float x1 = fmaxf(D[mt][nt][2 * h + 1] + bb1, 0.0f);
                float h0 = __bfloat162float(__float2bfloat16(x0));
                float h1 = __bfloat162float(__float2bfloat16(x1));
                *reinterpret_cast<uint32_t*>(Oh + row * AS + col) = bfpack(h0, h1);
                *reinterpret_cast<uint32_t*>(Ol + row * AS + col) =
                    bfpack(x0 - h0, x1 - h1);
            }
        }
    }
}

// ---------------- main persistent kernel ----------------
__global__ void __launch_bounds__(NTHREADS, 1) lv_tc_kernel(
    const float* __restrict__ W0, const float* __restrict__ b0,
    const float* __restrict__ b1, const float* __restrict__ b2,
    const float* __restrict__ b3,
    const float* __restrict__ obs_init, const float* __restrict__ feature_init,
    const float* __restrict__ tn_store, const float* __restrict__ x1_store,
    const float* __restrict__ x2_store, const float* __restrict__ path_seed,
    float* __restrict__ out) {
    extern __shared__ __align__(16) unsigned char smem_raw[];
    __nv_bfloat16* Ah = reinterpret_cast<__nv_bfloat16*>(smem_raw);
    __nv_bfloat16* Al = Ah + M_CTA * AS;
    __nv_bfloat16* Bh = Al + M_CTA * AS;
    __nv_bfloat16* Bl = Bh + M_CTA * AS;
    float* w0_sh = reinterpret_cast<float*>(Bl + M_CTA * AS);
    float* b0_sh = w0_sh + 8 * HH;
    float* b1_sh = b0_sh + HH;
    float* b2_sh = b1_sh + HH;
    float* b3_sh = b2_sh + HH;       // 8
    float* out5  = b3_sh + 8;        // 32*8
    float* st_sh = out5 + M_CTA * 8; // 64
    float* inp0  = st_sh + 64;       // 32*8
    uint2* w3f   = reinterpret_cast<uint2*>(inp0 + M_CTA * 8);  // 1024 uint2

    const int tid = threadIdx.x;
    const int warp = tid >> 5, lane = tid & 31;
    const int row0 = blockIdx.x * M_CTA;

    // one-time staging
    for (int i = tid; i < 8 * HH; i += NTHREADS) w0_sh[i] = W0[i];
    if (tid < HH) { b0_sh[tid] = b0[tid]; b1_sh[tid] = b1[tid]; b2_sh[tid] = b2[tid]; }
    if (tid < 8) b3_sh[tid] = (tid < 5) ? b3[tid] : 0.0f;
    if (tid < M_CTA * 2) st_sh[tid] = obs_init[row0 * 2 + tid];
    if (tid < M_CTA * 8) {
        int r = tid >> 3, k = tid & 7;
        inp0[tid] = (k < 2) ? obs_init[(row0 + r) * 2 + k]
                            : feature_init[(row0 + r) * 6 + (k - 2)];
    }
    // layer-3 fragments -> smem once: hi at [0,512), lo at [512,1024)
    for (int i = tid; i < 1024; i += NTHREADS)
        w3f[i] = (i < 512) ? g_W3h[i] : g_W3l[i - 512];
    float t_reg = __ldg(feature_init);   // t0 = feature_init[0,0,0]
    __syncthreads();

    // layer-0 mapping: 512 threads -> col n = tid&255, row half rh = tid>>8
    const int l0n  = tid & 255;
    const int l0r0 = (tid >> 8) * 16;    // rows [l0r0, l0r0+16)

#pragma unroll 1
    for (int s = 0; s < NSTEPS; s++) {
        // ---- layer 0 (scalar fp32) -> Ah/Al
        {
            const int n = l0n;
            if (s == 0) {
#pragma unroll 4
                for (int rr = 0; rr < 16; rr++) {
                    const int r = l0r0 + rr;
                    float a = b0_sh[n];
#pragma unroll
                    for (int k = 0; k < 8; k++)
                        a = fmaf(inp0[r * 8 + k], w0_sh[k * HH + n], a);
                    a = fmaxf(a, 0.0f);
                    float h = __bfloat162float(__float2bfloat16(a));
                    Ah[r * AS + n] = __float2bfloat16(a);
                    Al[r * AS + n] = __float2bfloat16(a - h);
                }
            } else {
                t_reg += DTC;   // exact sequential fp32 time accumulation
                const int i = s - 1;
                const float f_tn = __ldg(tn_store + i);
                const float f_x1 = __ldg(x1_store + i);
                const float f_x2 = __ldg(x2_store + i);
                float base = b0_sh[n];
                base = fmaf(t_reg, w0_sh[2 * HH + n], base);
                base = fmaf(f_tn,  w0_sh[3 * HH + n], base);
                base = fmaf(f_x1,  w0_sh[4 * HH + n], base);
                base = fmaf(f_x2,  w0_sh[5 * HH + n], base);
                base = fmaf(f_x1,  w0_sh[6 * HH + n], base);
                base = fmaf(f_x2,  w0_sh[7 * HH + n], base);
                const float wa = w0_sh[n], wb = w0_sh[HH + n];
#pragma unroll 4
                for (int rr = 0; rr < 16; rr++) {
                    const int r = l0r0 + rr;
                    float a = fmaf(st_sh[2 * r], wa, fmaf(st_sh[2 * r + 1], wb, base));
                    a = fmaxf(a, 0.0f);
                    float h = __bfloat162float(__float2bfloat16(a));
                    Ah[r * AS + n] = __float2bfloat16(a);
                    Al[r * AS + n] = __float2bfloat16(a - h);
                }
            }
        }
        __syncthreads();

        tc_layer(Ah, Al, Bh, Bl, g_W1h, g_W1l, b1_sh, warp, lane);
        __syncthreads();
        tc_layer(Bh, Bl, Ah, Al, g_W2h, g_W2l, b2_sh, warp, lane);
        __syncthreads();

        // ---- layer 3: (32 x 256) @ (256 x 5pad8), warps 0-1 (one m16 tile each)
        if (warp < 2) {
            float D[4] = {0.f, 0.f, 0.f, 0.f};
            const int arow = warp * 16 + (lane & 7) + ((lane >> 3) & 1) * 8;
            const int acol = (lane >> 4) * 8;
#pragma unroll
            for (int kt = 0; kt < 16; kt++) {
                uint32_t ah[4], al[4];
                ldsm4(ah, Ah + arow * AS + kt * 16 + acol);
                ldsm4(al, Al + arow * AS + kt * 16 + acol);
                uint2 bh = w3f[kt * 32 + lane];
                uint2 bl = w3f[512 + kt * 32 + lane];
                mma_bf16(D, ah, bh.x, bh.y);
                mma_bf16(D, ah, bl.x, bl.y);
                mma_bf16(D, al, bh.x, bh.y);
            }
            const int row = warp * 16 + (lane >> 2);
            const int col = (lane & 3) * 2;
            out5[row * 8 + col]           = D[0];
            out5[row * 8 + col + 1]       = D[1];
            out5[(row + 8) * 8 + col]     = D[2];
            out5[(row + 8) * 8 + col + 1] = D[3];
        }
        __syncthreads();

        // ---- SDE sample + global writes (fp32, exact reference semantics)
        if (tid < M_CTA) {
            const int r = tid, p = row0 + r;
            float mu0 = out5[r * 8 + 0] + b3_sh[0];
            float mu1 = out5[r * 8 + 1] + b3_sh[1];
            float s11 = softplusf(out5[r * 8 + 2] + b3_sh[2]);
            float s21 = out5[r * 8 + 3] + b3_sh[3];
            float s22 = softplusf(out5[r * 8 + 4] + b3_sh[4]);
            float st0 = st_sh[2 * r], st1 = st_sh[2 * r + 1];
            float2 e = __ldg(reinterpret_cast<const float2*>(path_seed) + s * PP + p);
            float n0v = softplusf(st0 + DTC * mu0 + SQRT_DTC * (s11 * e.x));
            float n1v = softplusf(st1 + DTC * mu1 + SQRT_DTC * (s21 * e.x + s22 * e.y));
            st_sh[2 * r]     = n0v;
            st_sh[2 * r + 1] = n1v;

            out[p * 202 + (s + 1)]       = n0v;
            out[p * 202 + 101 + (s + 1)] = n1v;
            if (s == 0) {
                out[p * 202 + 0]   = st0;
                out[p * 202 + 101] = st1;
            }
            int mb = PP * 202 + (p * 100 + s) * 2;
            out[mb + 0] = mu0;
            out[mb + 1] = mu1;
            int sb = PP * 202 + PP * 200 + (p * 100 + s) * 4;
            out[sb + 0] = s11;
            out[sb + 1] = 0.0f;
            out[sb + 2] = s21;
            out[sb + 3] = s22;
        }
        __syncthreads();
    }
}

extern "C" void kernel_launch(void* const* d_in, const int* in_sizes, int n_in,
                              void* d_out, int out_size) {
    const float* W0 = (const float*)d_in[0];
    const float* b0 = (const float*)d_in[1];
    const float* W1 = (const float*)d_in[2];
    const float* b1 = (const float*)d_in[3];
    const float* W2 = (const float*)d_in[4];
    const float* b2 = (const float*)d_in[5];
    const float* W3 = (const float*)d_in[6];
    const float* b3 = (const float*)d_in[7];
    const float* obs_init = (const float*)d_in[8];
    const float* feature_init = (const float*)d_in[9];
    const float* tn_store = (const float*)d_in[10];
    const float* x1_store = (const float*)d_in[11];
    const float* x2_store = (const float*)d_in[12];
    const float* path_seed = (const float*)d_in[13];
    float* out = (float*)d_out;

    // 1) split weights into hi/lo bf16 fragment arrays
    prep_kernel<<<130, 256>>>(W1, W2, W3);

    // 2) persistent 100-step trajectory kernel
    cudaFuncSetAttribute(lv_tc_kernel, cudaFuncAttributeMaxDynamicSharedMemorySize,
                         SMEM_BYTES);
    lv_tc_kernel<<<NCTA, NTHREADS, SMEM_BYTES>>>(
        W0, b0, b1, b2, b3, obs_init, feature_init,
        tn_store, x1_store, x2_store, path_seed, out);
}

// round 13
// speedup vs baseline: 1.6957x; 1.0351x over previous
#include <cuda_runtime.h>
#include <cuda_bf16.h>
#include <cstdint>

#define PP        4096
#define HH        256
#define NSTEPS    100
#define DTC       0.1f
#define SQRT_DTC  0.31622776601683794f
#define M_CTA     32
#define NCTA      (PP / M_CTA)   // 128
#define NTHREADS  512            // 16 warps, 2 n-tiles each
#define AS        264            // bf16 row stride (528B): conflict-free ldsm/STS

// smem: 4 act bufs (67584) + w0 (8192) + b0/b1/b2 (3072) + b3 (32)
//       + out5 (1024) + st (256) + inp0 (1024) + w3frag (8192) = 89376
#define SMEM_BYTES 89376

// Weight fragments in exact mma.m16n8k16 B-operand order: [k_tile][n8][lane] -> {b0,b1}
__device__ uint2 g_W1h[16 * 32 * 32];
__device__ uint2 g_W1l[16 * 32 * 32];
__device__ uint2 g_W2h[16 * 32 * 32];
__device__ uint2 g_W2l[16 * 32 * 32];
__device__ uint2 g_W3h[16 * 32];
__device__ uint2 g_W3l[16 * 32];

__device__ __forceinline__ float softplusf(float x) {
    return fmaxf(x, 0.0f) + log1pf(expf(-fabsf(x)));
}
__device__ __forceinline__ uint32_t bfpack(float a, float b) {
    __nv_bfloat162 v = __floats2bfloat162_rn(a, b);   // .x = a (low half)
    return *reinterpret_cast<uint32_t*>(&v);
}

// ---------------- prep: fp32 weights -> hi/lo bf16 fragment arrays ----------------
__global__ void prep_kernel(const float* __restrict__ W1,
                            const float* __restrict__ W2,
                            const float* __restrict__ W3) {
    const int idx = blockIdx.x * blockDim.x + threadIdx.x;
    const int TOT = 16 * 32 * 32;
    if (idx < 2 * TOT) {
        const int l = idx / TOT, r = idx % TOT;
        const int kt = r >> 10;
        const int n8 = (r >> 5) & 31;
        const int lane = r & 31;
        const int k0 = kt * 16 + (lane & 3) * 2;
        const int n = n8 * 8 + (lane >> 2);
        const float* W = l ? W2 : W1;
        float x[4];
        x[0] = W[(k0)     * HH + n];
        x[1] = W[(k0 + 1) * HH + n];
        x[2] = W[(k0 + 8) * HH + n];
        x[3] = W[(k0 + 9) * HH + n];
        float h[4], lo[4];
#pragma unroll
        for (int i = 0; i < 4; i++) {
            h[i]  = __bfloat162float(__float2bfloat16(x[i]));
            lo[i] = x[i] - h[i];
        }
        uint2 hv, lv;
        hv.x = bfpack(h[0], h[1]);  hv.y = bfpack(h[2], h[3]);
        lv.x = bfpack(lo[0], lo[1]); lv.y = bfpack(lo[2], lo[3]);
        if (l) { g_W2h[r] = hv; g_W2l[r] = lv; }
        else   { g_W1h[r] = hv; g_W1l[r] = lv; }
    } else if (idx < 2 * TOT + 512) {
        const int r = idx - 2 * TOT;
        const int kt = r >> 5, lane = r & 31;
        const int k0 = kt * 16 + (lane & 3) * 2;
        const int n = lane >> 2;
        float x[4] = {0.f, 0.f, 0.f, 0.f};
        if (n < 5) {
            x[0] = W3[(k0)     * 5 + n];
            x[1] = W3[(k0 + 1) * 5 + n];
            x[2] = W3[(k0 + 8) * 5 + n];
            x[3] = W3[(k0 + 9) * 5 + n];
        }
        float h[4], lo[4];
#pragma unroll
        for (int i = 0; i < 4; i++) {
            h[i]  = __bfloat162float(__float2bfloat16(x[i]));
            lo[i] = x[i] - h[i];
        }
        uint2 hv, lv;
        hv.x = bfpack(h[0], h[1]);  hv.y = bfpack(h[2], h[3]);
        lv.x = bfpack(lo[0], lo[1]); lv.y = bfpack(lo[2], lo[3]);
        g_W3h[r] = hv; g_W3l[r] = lv;
    }
}

// ---------------- tensor-core primitives ----------------
__device__ __forceinline__ void ldsm4(uint32_t* r, const __nv_bfloat16* p) {
    uint32_t addr = (uint32_t)__cvta_generic_to_shared(p);
    asm volatile("ldmatrix.sync.aligned.m8n8.x4.shared.b16 {%0,%1,%2,%3}, [%4];"
                 : "=r"(r[0]), "=r"(r[1]), "=r"(r[2]), "=r"(r[3]) : "r"(addr));
}
__device__ __forceinline__ void mma_bf16(float* d, const uint32_t* a,
                                         uint32_t b0, uint32_t b1) {
    asm volatile(
        "mma.sync.aligned.m16n8k16.row.col.f32.bf16.bf16.f32 "
        "{%0,%1,%2,%3}, {%4,%5,%6,%7}, {%8,%9}, {%0,%1,%2,%3};"
        : "+f"(d[0]), "+f"(d[1]), "+f"(d[2]), "+f"(d[3])
        : "r"(a[0]), "r"(a[1]), "r"(a[2]), "r"(a[3]), "r"(b0), "r"(b1));
}

// B fragments for one kt (2 n-tiles, hi+lo) and A fragments (2 m-tiles, hi+lo)
struct BFrag { uint2 bh[2], bl[2]; };
struct AFrag { uint32_t ah0[4], ah1[4], al0[4], al1[4]; };

__device__ __forceinline__ void load_B(BFrag& b, const uint2* __restrict__ bhp,
                                       const uint2* __restrict__ blp, int kt) {
    const uint2* bh = bhp + kt * 1024;
    const uint2* bl = blp + kt * 1024;
    b.bh[0] = __ldg(bh);      b.bh[1] = __ldg(bh + 32);
    b.bl[0] = __ldg(bl);      b.bl[1] = __ldg(bl + 32);
}
__device__ __forceinline__ void load_A(AFrag& a, const __nv_bfloat16* Ah,
                                       const __nv_bfloat16* Al, int arow, int co) {
    ldsm4(a.ah0, Ah + arow * AS + co);
    ldsm4(a.ah1, Ah + (arow + 16) * AS + co);
    ldsm4(a.al0, Al + arow * AS + co);
    ldsm4(a.al1, Al + (arow + 16) * AS + co);
}
__device__ __forceinline__ void mma_AB(float D[2][2][4], const AFrag& a,
                                       const BFrag& b) {
#pragma unroll
    for (int nt = 0; nt < 2; nt++) {
        mma_bf16(D[0][nt], a.ah0, b.bh[nt].x, b.bh[nt].y);
        mma_bf16(D[1][nt], a.ah1, b.bh[nt].x, b.bh[nt].y);
        mma_bf16(D[0][nt], a.ah0, b.bl[nt].x, b.bl[nt].y);
        mma_bf16(D[1][nt], a.ah1, b.bl[nt].x, b.bl[nt].y);
        mma_bf16(D[0][nt], a.al0, b.bh[nt].x, b.bh[nt].y);
        mma_bf16(D[1][nt], a.al1, b.bh[nt].x, b.bh[nt].y);
    }
}

// One 256->256 layer + bias + relu, 3-term split-bf16.
// 16 warps; warp w owns output cols [16w, 16w+16) (n-tiles 2w, 2w+1), 32 rows.
// B prefetched at distance 4 (covers ~250cyc L2 latency); A at distance 1.
__device__ __forceinline__ void tc_layer(
    const __nv_bfloat16* Ah, const __nv_bfloat16* Al,
    __nv_bfloat16* Oh, __nv_bfloat16* Ol,
    const uint2* __restrict__ Bh, const uint2* __restrict__ Bl,
    const float* b_sh, int warp, int lane) {
    float D[2][2][4];
#pragma unroll
    for (int mt = 0; mt < 2; mt++)
#pragma unroll
        for (int nt = 0; nt < 2; nt++)
#pragma unroll
            for (int i = 0; i < 4; i++) D[mt][nt][i] = 0.0f;

    const int arow = (lane & 7) + ((lane >> 3) & 1) * 8;
    const int acol = (lane >> 4) * 8;
    const uint2* bhp = Bh + 2 * warp * 32 + lane;   // + kt*1024 per tile
    const uint2* blp = Bl + 2 * warp * 32 + lane;

    BFrag B0, B1, B2, B3;
    AFrag A0, A1;
    load_B(B0, bhp, blp, 0);
    load_B(B1, bhp, blp, 1);
    load_B(B2, bhp, blp, 2);
    load_B(B3, bhp, blp, 3);
    load_A(A0, Ah, Al, arow, acol);

#pragma unroll
    for (int i = 0; i < 4; i++) {
        const int kt = 4 * i;
        // phase 0: compute kt, fetch A(kt+1), B(kt+4)
        load_A(A1, Ah, Al, arow, (kt + 1) * 16 + acol);
        mma_AB(D, A0, B0);
        if (i < 3) load_B(B0, bhp, blp, kt + 4);
        // phase 1
        load_A(A0, Ah, Al, arow, (kt + 2) * 16 + acol);
        mma_AB(D, A1, B1);
        if (i < 3) load_B(B1, bhp, blp, kt + 5);
        // phase 2
        load_A(A1, Ah, Al, arow, (kt + 3) * 16 + acol);
        mma_AB(D, A0, B2);
        if (i < 3) load_B(B2, bhp, blp, kt + 6);
        // phase 3
        if (i < 3) load_A(A0, Ah, Al, arow, (kt + 4) * 16 + acol);
        mma_AB(D, A1, B3);
        if (i < 3) load_B(B3, bhp, blp, kt + 7);
    }

    // epilogue: bias + relu + hi/lo split, conflict-free STS.32
    const int rbase = lane >> 2;
#pragma unroll
    for (int mt = 0; mt < 2; mt++) {
#pragma unroll
        for (int nt = 0; nt < 2; nt++) {
            const int col = (2 * warp + nt) * 8 + (lane & 3) * 2;
            const float bb0 = b_sh[col], bb1 = b_sh[col + 1];
#pragma unroll
            for (int h = 0; h < 2; h++) {
                const int row = mt * 16 + rbase + h * 8;
                float x0 = fmaxf(D[mt][nt][2 * h + 0] + bb0, 0.0f);
                float x1 = fmaxf(D[mt][nt][2 * h + 1] + bb1, 0.0f);
                float h0 = __bfloat162float(__float2bfloat16(x0));
                float h1 = __bfloat162float(__float2bfloat16(x1));
                *reinterpret_cast<uint32_t*>(Oh + row * AS + col) = bfpack(h0, h1);
                *reinterpret_cast<uint32_t*>(Ol + row * AS + col) =
                    bfpack(x0 - h0, x1 - h1);
            }
        }
    }
}

// ---------------- main persistent kernel ----------------
__global__ void __launch_bounds__(NTHREADS, 1) lv_tc_kernel(
    const float* __restrict__ W0, const float* __restrict__ b0,
    const float* __restrict__ b1, const float* __restrict__ b2,
    const float* __restrict__ b3,
    const float* __restrict__ obs_init, const float* __restrict__ feature_init,
    const float* __restrict__ tn_store, const float* __restrict__ x1_store,
    const float* __restrict__ x2_store, const float* __restrict__ path_seed,
    float* __restrict__ out) {
    extern __shared__ __align__(16) unsigned char smem_raw[];
    __nv_bfloat16* Ah = reinterpret_cast<__nv_bfloat16*>(smem_raw);
    __nv_bfloat16* Al = Ah + M_CTA * AS;
    __nv_bfloat16* Bh = Al + M_CTA * AS;
    __nv_bfloat16* Bl = Bh + M_CTA * AS;
    float* w0_sh = reinterpret_cast<float*>(Bl + M_CTA * AS);
    float* b0_sh = w0_sh + 8 * HH;
    float* b1_sh = b0_sh + HH;
    float* b2_sh = b1_sh + HH;
    float* b3_sh = b2_sh + HH;       // 8
    float* out5  = b3_sh + 8;        // 32*8
    float* st_sh = out5 + M_CTA * 8; // 64
    float* inp0  = st_sh + 64;       // 32*8
    uint2* w3f   = reinterpret_cast<uint2*>(inp0 + M_CTA * 8);  // 1024 uint2

    const int tid = threadIdx.x;
    const int warp = tid >> 5, lane = tid & 31;
    const int row0 = blockIdx.x * M_CTA;

    // one-time staging
    for (int i = tid; i < 8 * HH; i += NTHREADS) w0_sh[i] = W0[i];
    if (tid < HH) { b0_sh[tid] = b0[tid]; b1_sh[tid] = b1[tid]; b2_sh[tid] = b2[tid]; }
    if (tid < 8) b3_sh[tid] = (tid < 5) ? b3[tid] : 0.0f;
    if (tid < M_CTA * 2) st_sh[tid] = obs_init[row0 * 2 + tid];
    if (tid < M_CTA * 8) {
        int r = tid >> 3, k = tid & 7;
        inp0[tid] = (k < 2) ? obs_init[(row0 + r) * 2 + k]
                            : feature_init[(row0 + r) * 6 + (k - 2)];
    }
    // layer-3 fragments -> smem once: hi at [0,512), lo at [512,1024)
    for (int i = tid; i < 1024; i += NTHREADS)
        w3f[i] = (i < 512) ? g_W3h[i] : g_W3l[i - 512];
    float t_reg = __ldg(feature_init);   // t0 = feature_init[0,0,0]
    __syncthreads();

    // layer-0 mapping: 512 threads -> col n = tid&255, row half rh = tid>>8
    const int l0n  = tid & 255;
    const int l0r0 = (tid >> 8) * 16;    // rows [l0r0, l0r0+16)

#pragma unroll 1
    for (int s = 0; s < NSTEPS; s++) {
        // ---- layer 0 (scalar fp32) -> Ah/Al
        {
            const int n = l0n;
            if (s == 0) {
#pragma unroll 4
                for (int rr = 0; rr < 16; rr++) {
                    const int r = l0r0 + rr;
                    float a = b0_sh[n];
#pragma unroll
                    for (int k = 0; k < 8; k++)
                        a = fmaf(inp0[r * 8 + k], w0_sh[k * HH + n], a);
                    a = fmaxf(a, 0.0f);
                    float h = __bfloat162float(__float2bfloat16(a));
                    Ah[r * AS + n] = __float2bfloat16(a);
                    Al[r * AS + n] = __float2bfloat16(a - h);
                }
            } else {
                t_reg += DTC;   // exact sequential fp32 time accumulation
                const int i = s - 1;
                const float f_tn = __ldg(tn_store + i);
                const float f_x1 = __ldg(x1_store + i);
                const float f_x2 = __ldg(x2_store + i);
                float base = b0_sh[n];
                base = fmaf(t_reg, w0_sh[2 * HH + n], base);
                base = fmaf(f_tn,  w0_sh[3 * HH + n], base);
                base = fmaf(f_x1,  w0_sh[4 * HH + n], base);
                base = fmaf(f_x2,  w0_sh[5 * HH + n], base);
                base = fmaf(f_x1,  w0_sh[6 * HH + n], base);
                base = fmaf(f_x2,  w0_sh[7 * HH + n], base);
                const float wa = w0_sh[n], wb = w0_sh[HH + n];
#pragma unroll 4
                for (int rr = 0; rr < 16; rr++) {
                    const int r = l0r0 + rr;
                    float a = fmaf(st_sh[2 * r], wa, fmaf(st_sh[2 * r + 1], wb, base));
                    a = fmaxf(a, 0.0f);
                    float h = __bfloat162float(__float2bfloat16(a));
                    Ah[r * AS + n] = __float2bfloat16(a);
                    Al[r * AS + n] = __float2bfloat16(a - h);
                }
            }
        }
        __syncthreads();

        tc_layer(Ah, Al, Bh, Bl, g_W1h, g_W1l, b1_sh, warp, lane);
        __syncthreads();
        tc_layer(Bh, Bl, Ah, Al, g_W2h, g_W2l, b2_sh, warp, lane);
        __syncthreads();

        // ---- layer 3: (32 x 256) @ (256 x 5pad8), warps 0-1 (one m16 tile each)
        if (warp < 2) {
            float D[4] = {0.f, 0.f, 0.f, 0.f};
            const int arow = warp * 16 + (lane & 7) + ((lane >> 3) & 1) * 8;
            const int acol = (lane >> 4) * 8;
#pragma unroll
            for (int kt = 0; kt < 16; kt++) {
                uint32_t ah[4], al[4];
                ldsm4(ah, Ah + arow * AS + kt * 16 + acol);
                ldsm4(al, Al + arow * AS + kt * 16 + acol);
                uint2 bh = w3f[kt * 32 + lane];
                uint2 bl = w3f[512 + kt * 32 + lane];
                mma_bf16(D, ah, bh.x, bh.y);
                mma_bf16(D, ah, bl.x, bl.y);
                mma_bf16(D, al, bh.x, bh.y);
            }
            const int row = warp * 16 + (lane >> 2);
            const int col = (lane & 3) * 2;
            out5[row * 8 + col]           = D[0];
            out5[row * 8 + col + 1]       = D[1];
            out5[(row + 8) * 8 + col]     = D[2];
            out5[(row + 8) * 8 + col + 1] = D[3];
        }
        __syncthreads();

        // ---- SDE sample + global writes (fp32, exact reference semantics)
        // one thread per (particle, dim): 64 threads
        if (tid < M_CTA * 2) {
            const int r = tid >> 1, d = tid & 1, p = row0 + r;
            float2 e = __ldg(reinterpret_cast<const float2*>(path_seed) + s * PP + p);
            const int mb = PP * 202 + (p * 100 + s) * 2;
            const int sb = PP * 202 + PP * 200 + (p * 100 + s) * 4;
            if (d == 0) {
                float mu0 = out5[r * 8 + 0] + b3_sh[0];
                float s11 = softplusf(out5[r * 8 + 2] + b3_sh[2]);
                float st0 = st_sh[2 * r];
                float n0v = softplusf(st0 + DTC * mu0 + SQRT_DTC * (s11 * e.x));
                st_sh[2 * r] = n0v;
                out[p * 202 + (s + 1)] = n0v;
                if (s == 0) out[p * 202 + 0] = st0;
                out[mb + 0] = mu0;
                out[sb + 0] = s11;
                out[sb + 1] = 0.0f;
            } else {
                float mu1 = out5[r * 8 + 1] + b3_sh[1];
                float s21 = out5[r * 8 + 3] + b3_sh[3];
                float s22 = softplusf(out5[r * 8 + 4] + b3_sh[4]);
                float st1 = st_sh[2 * r + 1];
                float n1v = softplusf(st1 + DTC * mu1 + SQRT_DTC * (s21 * e.x + s22 * e.y));
                st_sh[2 * r + 1] = n1v;
                out[p * 202 + 101 + (s + 1)] = n1v;
                if (s == 0) out[p * 202 + 101] = st1;
                out[mb + 1] = mu1;
                out[sb + 2] = s21;
                out[sb + 3] = s22;
            }
        }
        __syncthreads();
    }
}

extern "C" void kernel_launch(void* const* d_in, const int* in_sizes, int n_in,
                              void* d_out, int out_size) {
    const float* W0 = (const float*)d_in[0];
    const float* b0 = (const float*)d_in[1];
    const float* W1 = (const float*)d_in[2];
    const float* b1 = (const float*)d_in[3];
    const float* W2 = (const float*)d_in[4];
    const float* b2 = (const float*)d_in[5];
    const float* W3 = (const float*)d_in[6];
    const float* b3 = (const float*)d_in[7];
    const float* obs_init = (const float*)d_in[8];
    const float* feature_init = (const float*)d_in[9];
    const float* tn_store = (const float*)d_in[10];
    const float* x1_store = (const float*)d_in[11];
    const float* x2_store = (const float*)d_in[12];
    const float* path_seed = (const float*)d_in[13];
    float* out = (float*)d_out;

    // 1) split weights into hi/lo bf16 fragment arrays
    prep_kernel<<<130, 256>>>(W1, W2, W3);

    // 2) persistent 100-step trajectory kernel
    cudaFuncSetAttribute(lv_tc_kernel, cudaFuncAttributeMaxDynamicSharedMemorySize,
                         SMEM_BYTES);
    lv_tc_kernel<<<NCTA, NTHREADS, SMEM_BYTES>>>(
        W0, b0, b1, b2, b3, obs_init, feature_init,
        tn_store, x1_store, x2_store, path_seed, out);
}